// round 7
// baseline (speedup 1.0000x reference)
#include <cuda_runtime.h>
#include <cuda_bf16.h>

#define BDIM 2
#define NSEQ 2048
#define DMODEL 256
#define HHEADS 8
#define DH 32
#define MROWS (BDIM*NSEQ)   // 4096
#define NBH (BDIM*HHEADS)   // 16

#define LOG2E 1.4426950408889634
#define QSCALE ((float)(1.4426950408889634/5.656854249492381))  // log2e/sqrt(32)

typedef unsigned long long u64;
typedef unsigned int u32;

// ---------------- scratch (__device__ globals; no allocations) --------------
__device__ __align__(16) __nv_bfloat16 g_Qhi[NBH*NSEQ*DH];
__device__ __align__(16) __nv_bfloat16 g_Qlo[NBH*NSEQ*DH];
__device__ __align__(16) __nv_bfloat16 g_Khi[NBH*NSEQ*DH];
__device__ __align__(16) __nv_bfloat16 g_Klo[NBH*NSEQ*DH];
__device__ __align__(16) __nv_bfloat16 g_Vhi[NBH*NSEQ*DH];   // [bh][n][d]
__device__ __align__(16) __nv_bfloat16 g_Vlo[NBH*NSEQ*DH];
__device__ __align__(16) __nv_bfloat16 g_Ohi[MROWS*DMODEL];
__device__ __align__(16) __nv_bfloat16 g_Olo[MROWS*DMODEL];
__device__ __align__(16) __nv_bfloat16 g_xhi[MROWS*DMODEL];
__device__ __align__(16) __nv_bfloat16 g_xlo[MROWS*DMODEL];
__device__ __align__(16) __nv_bfloat16 g_wh[4*DMODEL*DMODEL]; // q,k,v,o
__device__ __align__(16) __nv_bfloat16 g_wl[4*DMODEL*DMODEL];

// ---------------- helpers ---------------------------------------------------
__device__ __forceinline__ u32 smem_u32(const void* p) {
    u32 a; asm("{ .reg .u64 t; cvta.to.shared.u64 t, %1; cvt.u32.u64 %0, t; }" : "=r"(a) : "l"(p));
    return a;
}
__device__ __forceinline__ void ldsm4(u32 &r0, u32 &r1, u32 &r2, u32 &r3, u32 a) {
    asm volatile("ldmatrix.sync.aligned.m8n8.x4.shared.b16 {%0,%1,%2,%3}, [%4];"
                 : "=r"(r0), "=r"(r1), "=r"(r2), "=r"(r3) : "r"(a));
}
__device__ __forceinline__ void ldsm4t(u32 &r0, u32 &r1, u32 &r2, u32 &r3, u32 a) {
    asm volatile("ldmatrix.sync.aligned.m8n8.x4.trans.shared.b16 {%0,%1,%2,%3}, [%4];"
                 : "=r"(r0), "=r"(r1), "=r"(r2), "=r"(r3) : "r"(a));
}
__device__ __forceinline__ void mma16816(float* d, const u32* a, u32 b0, u32 b1) {
    asm volatile("mma.sync.aligned.m16n8k16.row.col.f32.bf16.bf16.f32 "
                 "{%0,%1,%2,%3}, {%4,%5,%6,%7}, {%8,%9}, {%0,%1,%2,%3};"
                 : "+f"(d[0]), "+f"(d[1]), "+f"(d[2]), "+f"(d[3])
                 : "r"(a[0]), "r"(a[1]), "r"(a[2]), "r"(a[3]), "r"(b0), "r"(b1));
}
__device__ __forceinline__ float ex2(float x) {
    float r; asm("ex2.approx.ftz.f32 %0, %1;" : "=f"(r) : "f"(x)); return r;
}
__device__ __forceinline__ u32 packbf(float a, float b) {
    __nv_bfloat162 t = __float22bfloat162_rn(make_float2(a, b));   // low = a
    return *(u32*)&t;
}
__device__ __forceinline__ u32 packsplit(float v0, float v1, u32 &lw) {
    u32 hw = packbf(v0, v1);
    float e0 = __uint_as_float(hw << 16);
    float e1 = __uint_as_float(hw & 0xffff0000u);
    lw = packbf(v0 - e0, v1 - e1);
    return hw;
}

// ---------------------------------------------------------------------------
// Convert fp32 -> bf16 hi/lo: x and the 4 weight matrices.
// ---------------------------------------------------------------------------
__global__ __launch_bounds__(256) void convert_split(
    const float* __restrict__ x, const float* __restrict__ Wq,
    const float* __restrict__ Wk, const float* __restrict__ Wv,
    const float* __restrict__ Wo)
{
    const int z = blockIdx.z;
    const float* src; __nv_bfloat16 *dh, *dl; int count;
    if (z == 0) { src = x; dh = g_xhi; dl = g_xlo; count = MROWS * DMODEL; }
    else {
        src = (z == 1) ? Wq : (z == 2) ? Wk : (z == 3) ? Wv : Wo;
        dh = g_wh + (size_t)(z - 1) * DMODEL * DMODEL;
        dl = g_wl + (size_t)(z - 1) * DMODEL * DMODEL;
        count = DMODEL * DMODEL;
    }
    int i = (blockIdx.x * 256 + threadIdx.x) * 2;
    if (i >= count) return;
    float2 v = *(const float2*)(src + i);
    u32 lw, hw = packsplit(v.x, v.y, lw);
    *(u32*)(dh + i) = hw;
    *(u32*)(dl + i) = lw;
}

// ---------------------------------------------------------------------------
// Tensor-core projection: C = X @ W^T + bias, bf16 3-split, fp32 accum.
// mode = base_mode + blockIdx.z: 0=Q (scaled), 1=K, 2=V, 3=out (fp32).
// BM=64, BN=64, BK=32. 256 thr / 8 warps; warp (w&3)=row grp, (w>>2)=col grp.
// ---------------------------------------------------------------------------
#define PRB 80       // smem row stride bytes (32 bf16 + pad)
#define PXH 0
#define PXL 5120
#define PWH 10240
#define PWL 15360

__global__ __launch_bounds__(256, 3) void proj_tc(
    const float* __restrict__ bq, const float* __restrict__ bk,
    const float* __restrict__ bv, const float* __restrict__ bo,
    float* __restrict__ outf, int base_mode)
{
    __shared__ __align__(128) char sm[20480];
    const u32 sb = smem_u32(sm);
    const int mode = base_mode + blockIdx.z;
    const __nv_bfloat16 *Xh, *Xl;
    if (mode < 3) { Xh = g_xhi; Xl = g_xlo; } else { Xh = g_Ohi; Xl = g_Olo; }
    const __nv_bfloat16* Wh = g_wh + (size_t)mode * DMODEL * DMODEL;
    const __nv_bfloat16* Wl = g_wl + (size_t)mode * DMODEL * DMODEL;
    const float* bias = (mode == 0) ? bq : (mode == 1) ? bk : (mode == 2) ? bv : bo;

    const int tid = threadIdx.x, lane = tid & 31, w = tid >> 5;
    const int wr = w & 3, wc = w >> 2;
    const int row0 = blockIdx.y * 64, col0 = blockIdx.x * 64;

    const int xr = tid >> 2, xs = tid & 3;

    const __nv_bfloat16* pxh = Xh + (size_t)(row0 + xr) * DMODEL + xs * 8;
    const __nv_bfloat16* pxl = Xl + (size_t)(row0 + xr) * DMODEL + xs * 8;
    const __nv_bfloat16* pwh = Wh + (size_t)(col0 + xr) * DMODEL + xs * 8;
    const __nv_bfloat16* pwl = Wl + (size_t)(col0 + xr) * DMODEL + xs * 8;

    uint4 rxh = *(const uint4*)pxh, rxl = *(const uint4*)pxl;
    uint4 rwh = *(const uint4*)pwh, rwl = *(const uint4*)pwl;

    float acc[4][4] = {};
    const int j = lane >> 3, r = lane & 7;
    const u32 abase = sb + PXH + (u32)(16 * wr + (j & 1) * 8 + r) * PRB + (u32)(j >> 1) * 16;
    const u32 wbase = sb + PWH + (u32)(32 * wc + (lane & 15)) * PRB + (u32)(lane >> 4) * 16;

    for (int kt = 0; kt < 8; kt++) {
        __syncthreads();
        *(uint4*)(sm + PXH + xr * PRB + xs * 16) = rxh;
        *(uint4*)(sm + PXL + xr * PRB + xs * 16) = rxl;
        *(uint4*)(sm + PWH + xr * PRB + xs * 16) = rwh;
        *(uint4*)(sm + PWL + xr * PRB + xs * 16) = rwl;
        __syncthreads();
        if (kt < 7) {
            int ko = (kt + 1) * 32;
            rxh = *(const uint4*)(pxh + ko); rxl = *(const uint4*)(pxl + ko);
            rwh = *(const uint4*)(pwh + ko); rwl = *(const uint4*)(pwl + ko);
        }
        u32 ah[2][4], al[2][4];
        ldsm4(ah[0][0], ah[0][1], ah[0][2], ah[0][3], abase);
        ldsm4(ah[1][0], ah[1][1], ah[1][2], ah[1][3], abase + 32);
        ldsm4(al[0][0], al[0][1], al[0][2], al[0][3], abase + (PXL - PXH));
        ldsm4(al[1][0], al[1][1], al[1][2], al[1][3], abase + (PXL - PXH) + 32);
        #pragma unroll
        for (int ng = 0; ng < 2; ng++) {
            #pragma unroll
            for (int kc = 0; kc < 2; kc++) {
                u32 wb = wbase + (u32)(16 * ng) * PRB + kc * 32;
                u32 h0, h1, h2, h3, l0, l1, l2, l3;
                ldsm4(h0, h1, h2, h3, wb);
                ldsm4(l0, l1, l2, l3, wb + (PWL - PWH));
                mma16816(acc[2 * ng],     ah[kc], h0, h2);
                mma16816(acc[2 * ng],     ah[kc], l0, l2);
                mma16816(acc[2 * ng],     al[kc], h0, h2);
                mma16816(acc[2 * ng + 1], ah[kc], h1, h3);
                mma16816(acc[2 * ng + 1], ah[kc], l1, l3);
                mma16816(acc[2 * ng + 1], al[kc], h1, h3);
            }
        }
    }

    // epilogue
    const int g = lane >> 2, c = lane & 3;
    const int m0 = row0 + 16 * wr + g;
    #pragma unroll
    for (int half = 0; half < 2; half++) {
        int m = m0 + 8 * half;
        int bb = m >> 11, n = m & (NSEQ - 1);
        #pragma unroll
        for (int nn = 0; nn < 4; nn++) {
            int col = col0 + 32 * wc + 8 * nn + 2 * c;
            float v0 = acc[nn][2 * half + 0] + bias[col];
            float v1 = acc[nn][2 * half + 1] + bias[col + 1];
            if (mode == 3) {
                *(float2*)(outf + (size_t)m * DMODEL + col) = make_float2(v0, v1);
            } else {
                if (mode == 0) { v0 *= QSCALE; v1 *= QSCALE; }
                u32 lw, hw = packsplit(v0, v1, lw);
                int hh = col >> 5, d = col & 31;
                size_t idx = (((size_t)(bb * HHEADS + hh)) * NSEQ + n) * DH + d;
                __nv_bfloat16* dsth = (mode == 0) ? g_Qhi : (mode == 1) ? g_Khi : g_Vhi;
                __nv_bfloat16* dstl = (mode == 0) ? g_Qlo : (mode == 1) ? g_Klo : g_Vlo;
                *(u32*)(dsth + idx) = hw;
                *(u32*)(dstl + idx) = lw;
            }
        }
    }
}

// ---------------------------------------------------------------------------
// mma.sync flash attention, bf16 3-split, O in fp32 mma accumulators.
// Grid (16 q-tiles, 16 bh), 256 threads / 8 warps; warp owns 16 query rows.
// ---------------------------------------------------------------------------
#define ROWB 80
#define KH_OFF 0
#define KL_OFF 5120
#define VH_OFF 10240
#define VL_OFF 15360
#define QH_OFF 0
#define QL_OFF 10240

__global__ __launch_bounds__(256, 3) void attn_mma(
    const float* __restrict__ A,
    const float* __restrict__ W1, const float* __restrict__ b1,
    const float* __restrict__ W2, const float* __restrict__ b2)
{
    __shared__ __align__(128) char smem[20480];
    const u32 sb = smem_u32(smem);
    const int tid = threadIdx.x;
    const int lane = tid & 31, w = tid >> 5;
    const int bh = blockIdx.y, b = bh >> 3, h = bh & 7;
    const int q0 = blockIdx.x * 128;
    const int g = lane >> 2, c = lane & 3;

    // bias MLP coefficients (log2 domain)
    bool fastp = true;
    float cpl = 0.f, cnl = 0.f;
    #pragma unroll
    for (int j = 0; j < 8; j++) {
        float w1 = W1[j], w2v = W2[h * 8 + j];
        fastp = fastp && (b1[j] == 0.0f);
        float cc = w2v * w1;
        cpl += cc * (w1 > 0.f ? 1.0f : 0.01f);
        cnl += cc * (w1 < 0.f ? 1.0f : 0.01f);
    }
    const float b2raw = b2[h];
    const float b2hl = b2raw * (float)LOG2E;
    cpl *= (float)LOG2E; cnl *= (float)LOG2E;

    // ---- stage Q (hi/lo) into smem, extract A-fragments ----
    {
        int row = tid >> 1, seg = tid & 1;
        const uint4* sh = (const uint4*)(g_Qhi + ((size_t)bh * NSEQ + q0 + row) * DH + seg * 16);
        const uint4* sl = (const uint4*)(g_Qlo + ((size_t)bh * NSEQ + q0 + row) * DH + seg * 16);
        uint4 h0 = sh[0], h1 = sh[1];
        uint4 l0 = sl[0], l1 = sl[1];
        char* d0 = smem + QH_OFF + row * ROWB + seg * 32;
        *(uint4*)d0 = h0; *(uint4*)(d0 + 16) = h1;
        char* d1 = smem + QL_OFF + row * ROWB + seg * 32;
        *(uint4*)d1 = l0; *(uint4*)(d1 + 16) = l1;
    }
    __syncthreads();
    u32 qh[2][4], ql[2][4];
    {
        int j = lane >> 3, r = lane & 7;
        int qrow = 16 * w + (j & 1) * 8 + r;
        u32 base = sb + qrow * ROWB + ((j >> 1) * 8) * 2;
        ldsm4(qh[0][0], qh[0][1], qh[0][2], qh[0][3], base + QH_OFF);
        ldsm4(qh[1][0], qh[1][1], qh[1][2], qh[1][3], base + QH_OFF + 32);
        ldsm4(ql[0][0], ql[0][1], ql[0][2], ql[0][3], base + QL_OFF);
        ldsm4(ql[1][0], ql[1][1], ql[1][2], ql[1][3], base + QL_OFF + 32);
    }

    const __nv_bfloat16* Kh = g_Khi + (size_t)bh * NSEQ * DH;
    const __nv_bfloat16* Kl = g_Klo + (size_t)bh * NSEQ * DH;
    const __nv_bfloat16* Vh = g_Vhi + (size_t)bh * NSEQ * DH;
    const __nv_bfloat16* Vl = g_Vlo + (size_t)bh * NSEQ * DH;
    const int lrow = tid >> 2, lq = tid & 3;
    const size_t loff = (size_t)lrow * DH + lq * 8;
    const u32 sdst = lrow * ROWB + lq * 16;

    const float* Ar = A + ((size_t)b * NSEQ + q0 + 16 * w + g) * NSEQ;

    float o[4][4] = {};
    float l0s = 0.f, l1s = 0.f;

    for (int kt = 0; kt < NSEQ / 64; kt++) {
        size_t off2 = (size_t)kt * 64 * DH + loff;
        uint4 tkh = *(const uint4*)(Kh + off2);
        uint4 tkl = *(const uint4*)(Kl + off2);
        uint4 tvh = *(const uint4*)(Vh + off2);
        uint4 tvl = *(const uint4*)(Vl + off2);
        __syncthreads();
        *(uint4*)(smem + KH_OFF + sdst) = tkh;
        *(uint4*)(smem + KL_OFF + sdst) = tkl;
        *(uint4*)(smem + VH_OFF + sdst) = tvh;
        *(uint4*)(smem + VL_OFF + sdst) = tvl;
        __syncthreads();
        const int k0 = kt * 64;

        // ---- S = QK^T (3-split) + bias, exp2, pack P frags ----
        u32 ph[8][2], pl[8][2];
        float2 a01 = *(const float2*)(Ar + k0 + 2 * c);
        float2 a23 = *(const float2*)(Ar + 8 * NSEQ + k0 + 2 * c);
        #pragma unroll
        for (int nt = 0; nt < 8; nt++) {
            u32 kaddr = sb + KH_OFF + (8 * nt + (lane & 7)) * ROWB + (lane >> 3) * 16;
            u32 kb0, kb1, kb2, kb3, kc0, kc1, kc2, kc3;
            ldsm4(kb0, kb1, kb2, kb3, kaddr);
            ldsm4(kc0, kc1, kc2, kc3, kaddr + (KL_OFF - KH_OFF));
            float s[4] = {0.f, 0.f, 0.f, 0.f};
            mma16816(s, qh[0], kb0, kb1);
            mma16816(s, qh[1], kb2, kb3);
            mma16816(s, ql[0], kb0, kb1);
            mma16816(s, ql[1], kb2, kb3);
            mma16816(s, qh[0], kc0, kc1);
            mma16816(s, qh[1], kc2, kc3);
            float2 na01, na23;
            if (nt < 7) {
                na01 = *(const float2*)(Ar + k0 + 8 * (nt + 1) + 2 * c);
                na23 = *(const float2*)(Ar + 8 * NSEQ + k0 + 8 * (nt + 1) + 2 * c);
            }
            float av[4] = { a01.x, a01.y, a23.x, a23.y };
            float p[4];
            #pragma unroll
            for (int e = 0; e < 4; e++) {
                float a = av[e];
                float bias;
                if (fastp) {
                    bias = fmaf(a, a > 0.f ? cpl : cnl, b2hl);
                } else {
                    float t = 0.f;
                    #pragma unroll
                    for (int jj = 0; jj < 8; jj++) {
                        float u = fmaf(a, W1[jj], b1[jj]);
                        u = fmaxf(u, 0.01f * u);
                        t = fmaf(W2[h * 8 + jj], u, t);
                    }
                    bias = (t + b2raw) * (float)LOG2E;
                }
                p[e] = ex2(s[e] + bias);
            }
            l0s += p[0] + p[1];
            l1s += p[2] + p[3];
            ph[nt][0] = packsplit(p[0], p[1], pl[nt][0]);
            ph[nt][1] = packsplit(p[2], p[3], pl[nt][1]);
            a01 = na01; a23 = na23;
        }

        // ---- O += P V (3-split), paired m16n8k16 over 16-key chunks ----
        #pragma unroll
        for (int t = 0; t < 4; t++) {
            u32 va0 = sb + VH_OFF + (16 * t + (lane & 7)) * ROWB + (lane >> 3) * 16;
            u32 va1 = va0 + 8 * ROWB;
            u32 vh0a, vh1a, vh2a, vh3a, vh0b, vh1b, vh2b, vh3b;
            u32 vl0a, vl1a, vl2a, vl3a, vl0b, vl1b, vl2b, vl3b;
            ldsm4t(vh0a, vh1a, vh2a, vh3a, va0);
            ldsm4t(vh0b, vh1b, vh2b, vh3b, va1);
            ldsm4t(vl0a, vl1a, vl2a, vl3a, va0 + (VL_OFF - VH_OFF));
            ldsm4t(vl0b, vl1b, vl2b, vl3b, va1 + (VL_OFF - VH_OFF));
            u32 Ah[4] = { ph[2 * t][0], ph[2 * t][1], ph[2 * t + 1][0], ph[2 * t + 1][1] };
            u32 Al[4] = { pl[2 * t][0], pl[2 * t][1], pl[2 * t + 1][0], pl[2 * t + 1][1] };
            mma16816(o[0], Ah, vh0a, vh0b);
            mma16816(o[1], Ah, vh1a, vh1b);
            mma16816(o[2], Ah, vh2a, vh2b);
            mma16816(o[3], Ah, vh3a, vh3b);
            mma16816(o[0], Ah, vl0a, vl0b);
            mma16816(o[1], Ah, vl1a, vl1b);
            mma16816(o[2], Ah, vl2a, vl2b);
            mma16816(o[3], Ah, vl3a, vl3b);
            mma16816(o[0], Al, vh0a, vh0b);
            mma16816(o[1], Al, vh1a, vh1b);
            mma16816(o[2], Al, vh2a, vh2b);
            mma16816(o[3], Al, vh3a, vh3b);
        }
    }

    // ---- reduce row sums across the 4 lanes of each row, write O hi/lo ----
    l0s += __shfl_xor_sync(0xffffffffu, l0s, 1);
    l0s += __shfl_xor_sync(0xffffffffu, l0s, 2);
    l1s += __shfl_xor_sync(0xffffffffu, l1s, 1);
    l1s += __shfl_xor_sync(0xffffffffu, l1s, 2);
    float i0 = 1.0f / l0s, i1 = 1.0f / l1s;
    int r0g = q0 + 16 * w + g;
    size_t base0 = ((size_t)b * NSEQ + r0g) * DMODEL + h * DH;
    size_t base1 = base0 + 8 * DMODEL;
    #pragma unroll
    for (int ng = 0; ng < 4; ng++) {
        u32 lw, hw;
        hw = packsplit(o[ng][0] * i0, o[ng][1] * i0, lw);
        *(u32*)(g_Ohi + base0 + 8 * ng + 2 * c) = hw;
        *(u32*)(g_Olo + base0 + 8 * ng + 2 * c) = lw;
        hw = packsplit(o[ng][2] * i1, o[ng][3] * i1, lw);
        *(u32*)(g_Ohi + base1 + 8 * ng + 2 * c) = hw;
        *(u32*)(g_Olo + base1 + 8 * ng + 2 * c) = lw;
    }
}

extern "C" void kernel_launch(void* const* d_in, const int* in_sizes, int n_in,
                              void* d_out, int out_size)
{
    const float* x  = (const float*)d_in[0];
    const float* A  = (const float*)d_in[1];
    const float* Wq = (const float*)d_in[2];
    const float* bq = (const float*)d_in[3];
    const float* Wk = (const float*)d_in[4];
    const float* bk = (const float*)d_in[5];
    const float* Wv = (const float*)d_in[6];
    const float* bv = (const float*)d_in[7];
    const float* Wo = (const float*)d_in[8];
    const float* bo = (const float*)d_in[9];
    const float* W1 = (const float*)d_in[10];
    const float* b1 = (const float*)d_in[11];
    const float* W2 = (const float*)d_in[12];
    const float* b2 = (const float*)d_in[13];
    float* out = (float*)d_out;

    convert_split<<<dim3(2048, 1, 5), 256>>>(x, Wq, Wk, Wv, Wo);
    proj_tc<<<dim3(DMODEL / 64, MROWS / 64, 3), 256>>>(bq, bk, bv, bo, out, 0);
    attn_mma<<<dim3(NSEQ / 128, NBH), 256>>>(A, W1, b1, W2, b2);
    proj_tc<<<dim3(DMODEL / 64, MROWS / 64, 1), 256>>>(bq, bk, bv, bo, out, 3);
}

// round 8
// speedup vs baseline: 1.3037x; 1.3037x over previous
#include <cuda_runtime.h>
#include <cuda_bf16.h>

#define BDIM 2
#define NSEQ 2048
#define DMODEL 256
#define HHEADS 8
#define DH 32
#define MROWS (BDIM*NSEQ)   // 4096
#define NBH (BDIM*HHEADS)   // 16

#define LOG2E 1.4426950408889634
#define QSCALE ((float)(1.4426950408889634/5.656854249492381))  // log2e/sqrt(32)

typedef unsigned long long u64;
typedef unsigned int u32;

// ---------------- scratch (__device__ globals; no allocations) --------------
__device__ __align__(16) __nv_bfloat16 g_Qhi[NBH*NSEQ*DH];
__device__ __align__(16) __nv_bfloat16 g_Qlo[NBH*NSEQ*DH];
__device__ __align__(16) __nv_bfloat16 g_Khi[NBH*NSEQ*DH];
__device__ __align__(16) __nv_bfloat16 g_Klo[NBH*NSEQ*DH];
__device__ __align__(16) __nv_bfloat16 g_Vhi[NBH*NSEQ*DH];   // [bh][n][d]
__device__ __align__(16) __nv_bfloat16 g_Vlo[NBH*NSEQ*DH];
__device__ __align__(16) __nv_bfloat16 g_Ohi[MROWS*DMODEL];
__device__ __align__(16) __nv_bfloat16 g_Olo[MROWS*DMODEL];
__device__ __align__(16) __nv_bfloat16 g_xhi[MROWS*DMODEL];
__device__ __align__(16) __nv_bfloat16 g_xlo[MROWS*DMODEL];
__device__ __align__(16) __nv_bfloat16 g_wh[4*DMODEL*DMODEL]; // q,k,v,o
__device__ __align__(16) __nv_bfloat16 g_wl[4*DMODEL*DMODEL];

// ---------------- helpers ---------------------------------------------------
__device__ __forceinline__ u32 smem_u32(const void* p) {
    u32 a; asm("{ .reg .u64 t; cvta.to.shared.u64 t, %1; cvt.u32.u64 %0, t; }" : "=r"(a) : "l"(p));
    return a;
}
__device__ __forceinline__ void ldsm4(u32 &r0, u32 &r1, u32 &r2, u32 &r3, u32 a) {
    asm volatile("ldmatrix.sync.aligned.m8n8.x4.shared.b16 {%0,%1,%2,%3}, [%4];"
                 : "=r"(r0), "=r"(r1), "=r"(r2), "=r"(r3) : "r"(a));
}
__device__ __forceinline__ void ldsm4t(u32 &r0, u32 &r1, u32 &r2, u32 &r3, u32 a) {
    asm volatile("ldmatrix.sync.aligned.m8n8.x4.trans.shared.b16 {%0,%1,%2,%3}, [%4];"
                 : "=r"(r0), "=r"(r1), "=r"(r2), "=r"(r3) : "r"(a));
}
__device__ __forceinline__ void mma16816(float* d, const u32* a, u32 b0, u32 b1) {
    asm volatile("mma.sync.aligned.m16n8k16.row.col.f32.bf16.bf16.f32 "
                 "{%0,%1,%2,%3}, {%4,%5,%6,%7}, {%8,%9}, {%0,%1,%2,%3};"
                 : "+f"(d[0]), "+f"(d[1]), "+f"(d[2]), "+f"(d[3])
                 : "r"(a[0]), "r"(a[1]), "r"(a[2]), "r"(a[3]), "r"(b0), "r"(b1));
}
__device__ __forceinline__ float ex2(float x) {
    float r; asm("ex2.approx.ftz.f32 %0, %1;" : "=f"(r) : "f"(x)); return r;
}
__device__ __forceinline__ u32 packbf(float a, float b) {
    __nv_bfloat162 t = __float22bfloat162_rn(make_float2(a, b));   // low = a
    return *(u32*)&t;
}
__device__ __forceinline__ u32 packsplit(float v0, float v1, u32 &lw) {
    u32 hw = packbf(v0, v1);
    float e0 = __uint_as_float(hw << 16);
    float e1 = __uint_as_float(hw & 0xffff0000u);
    lw = packbf(v0 - e0, v1 - e1);
    return hw;
}

// ---------------------------------------------------------------------------
// Convert fp32 -> bf16 hi/lo: x and the 4 weight matrices.
// ---------------------------------------------------------------------------
__global__ __launch_bounds__(256) void convert_split(
    const float* __restrict__ x, const float* __restrict__ Wq,
    const float* __restrict__ Wk, const float* __restrict__ Wv,
    const float* __restrict__ Wo)
{
    const int z = blockIdx.z;
    const float* src; __nv_bfloat16 *dh, *dl; int count;
    if (z == 0) { src = x; dh = g_xhi; dl = g_xlo; count = MROWS * DMODEL; }
    else {
        src = (z == 1) ? Wq : (z == 2) ? Wk : (z == 3) ? Wv : Wo;
        dh = g_wh + (size_t)(z - 1) * DMODEL * DMODEL;
        dl = g_wl + (size_t)(z - 1) * DMODEL * DMODEL;
        count = DMODEL * DMODEL;
    }
    int i = (blockIdx.x * 256 + threadIdx.x) * 2;
    if (i >= count) return;
    float2 v = *(const float2*)(src + i);
    u32 lw, hw = packsplit(v.x, v.y, lw);
    *(u32*)(dh + i) = hw;
    *(u32*)(dl + i) = lw;
}

// ---------------------------------------------------------------------------
// Tensor-core projection: C = X @ W^T + bias, bf16 3-split, fp32 accum.
// mode = base_mode + blockIdx.z: 0=Q (scaled), 1=K, 2=V, 3=out (fp32).
// BM=64, BN=64, BK=32. 256 thr / 8 warps.
// ---------------------------------------------------------------------------
#define PRB 80       // smem row stride bytes (32 bf16 + pad)
#define PXH 0
#define PXL 5120
#define PWH 10240
#define PWL 15360

__global__ __launch_bounds__(256, 3) void proj_tc(
    const float* __restrict__ bq, const float* __restrict__ bk,
    const float* __restrict__ bv, const float* __restrict__ bo,
    float* __restrict__ outf, int base_mode)
{
    __shared__ __align__(128) char sm[20480];
    const u32 sb = smem_u32(sm);
    const int mode = base_mode + blockIdx.z;
    const __nv_bfloat16 *Xh, *Xl;
    if (mode < 3) { Xh = g_xhi; Xl = g_xlo; } else { Xh = g_Ohi; Xl = g_Olo; }
    const __nv_bfloat16* Wh = g_wh + (size_t)mode * DMODEL * DMODEL;
    const __nv_bfloat16* Wl = g_wl + (size_t)mode * DMODEL * DMODEL;
    const float* bias = (mode == 0) ? bq : (mode == 1) ? bk : (mode == 2) ? bv : bo;

    const int tid = threadIdx.x, lane = tid & 31, w = tid >> 5;
    const int wr = w & 3, wc = w >> 2;
    const int row0 = blockIdx.y * 64, col0 = blockIdx.x * 64;

    const int xr = tid >> 2, xs = tid & 3;

    const __nv_bfloat16* pxh = Xh + (size_t)(row0 + xr) * DMODEL + xs * 8;
    const __nv_bfloat16* pxl = Xl + (size_t)(row0 + xr) * DMODEL + xs * 8;
    const __nv_bfloat16* pwh = Wh + (size_t)(col0 + xr) * DMODEL + xs * 8;
    const __nv_bfloat16* pwl = Wl + (size_t)(col0 + xr) * DMODEL + xs * 8;

    uint4 rxh = *(const uint4*)pxh, rxl = *(const uint4*)pxl;
    uint4 rwh = *(const uint4*)pwh, rwl = *(const uint4*)pwl;

    float acc[4][4] = {};
    const int j = lane >> 3, r = lane & 7;
    const u32 abase = sb + PXH + (u32)(16 * wr + (j & 1) * 8 + r) * PRB + (u32)(j >> 1) * 16;
    const u32 wbase = sb + PWH + (u32)(32 * wc + (lane & 15)) * PRB + (u32)(lane >> 4) * 16;

    for (int kt = 0; kt < 8; kt++) {
        __syncthreads();
        *(uint4*)(sm + PXH + xr * PRB + xs * 16) = rxh;
        *(uint4*)(sm + PXL + xr * PRB + xs * 16) = rxl;
        *(uint4*)(sm + PWH + xr * PRB + xs * 16) = rwh;
        *(uint4*)(sm + PWL + xr * PRB + xs * 16) = rwl;
        __syncthreads();
        if (kt < 7) {
            int ko = (kt + 1) * 32;
            rxh = *(const uint4*)(pxh + ko); rxl = *(const uint4*)(pxl + ko);
            rwh = *(const uint4*)(pwh + ko); rwl = *(const uint4*)(pwl + ko);
        }
        u32 ah[2][4], al[2][4];
        ldsm4(ah[0][0], ah[0][1], ah[0][2], ah[0][3], abase);
        ldsm4(ah[1][0], ah[1][1], ah[1][2], ah[1][3], abase + 32);
        ldsm4(al[0][0], al[0][1], al[0][2], al[0][3], abase + (PXL - PXH));
        ldsm4(al[1][0], al[1][1], al[1][2], al[1][3], abase + (PXL - PXH) + 32);
        #pragma unroll
        for (int ng = 0; ng < 2; ng++) {
            #pragma unroll
            for (int kc = 0; kc < 2; kc++) {
                u32 wb = wbase + (u32)(16 * ng) * PRB + kc * 32;
                u32 h0, h1, h2, h3, l0, l1, l2, l3;
                ldsm4(h0, h1, h2, h3, wb);
                ldsm4(l0, l1, l2, l3, wb + (PWL - PWH));
                mma16816(acc[2 * ng],     ah[kc], h0, h2);
                mma16816(acc[2 * ng],     ah[kc], l0, l2);
                mma16816(acc[2 * ng],     al[kc], h0, h2);
                mma16816(acc[2 * ng + 1], ah[kc], h1, h3);
                mma16816(acc[2 * ng + 1], ah[kc], l1, l3);
                mma16816(acc[2 * ng + 1], al[kc], h1, h3);
            }
        }
    }

    // epilogue
    const int g = lane >> 2, c = lane & 3;
    const int m0 = row0 + 16 * wr + g;
    #pragma unroll
    for (int half = 0; half < 2; half++) {
        int m = m0 + 8 * half;
        int bb = m >> 11, n = m & (NSEQ - 1);
        #pragma unroll
        for (int nn = 0; nn < 4; nn++) {
            int col = col0 + 32 * wc + 8 * nn + 2 * c;
            float v0 = acc[nn][2 * half + 0] + bias[col];
            float v1 = acc[nn][2 * half + 1] + bias[col + 1];
            if (mode == 3) {
                *(float2*)(outf + (size_t)m * DMODEL + col) = make_float2(v0, v1);
            } else {
                if (mode == 0) { v0 *= QSCALE; v1 *= QSCALE; }
                u32 lw, hw = packsplit(v0, v1, lw);
                int hh = col >> 5, d = col & 31;
                size_t idx = (((size_t)(bb * HHEADS + hh)) * NSEQ + n) * DH + d;
                __nv_bfloat16* dsth = (mode == 0) ? g_Qhi : (mode == 1) ? g_Khi : g_Vhi;
                __nv_bfloat16* dstl = (mode == 0) ? g_Qlo : (mode == 1) ? g_Klo : g_Vlo;
                *(u32*)(dsth + idx) = hw;
                *(u32*)(dstl + idx) = lw;
            }
        }
    }
}

// ---------------------------------------------------------------------------
// mma.sync flash attention, bf16 3-split, fp32 accumulators.
// Double-buffered K/V smem (2 x 20KB); one __syncthreads per k-tile;
// register prefetch of next tile overlapped with current tile's compute.
// Grid (16 q-tiles, 16 bh), 256 threads / 8 warps; warp owns 16 query rows.
// ---------------------------------------------------------------------------
#define ROWB 80
#define BUFB 20480          // bytes per K/V buffer
#define KH_OFF 0
#define KL_OFF 5120
#define VH_OFF 10240
#define VL_OFF 15360
// Q staging (pre-loop) lives in buffer 1:
#define QH_OFF (BUFB + 0)
#define QL_OFF (BUFB + 10240)

__global__ __launch_bounds__(256, 2) void attn_mma(
    const float* __restrict__ A,
    const float* __restrict__ W1, const float* __restrict__ b1,
    const float* __restrict__ W2, const float* __restrict__ b2)
{
    __shared__ __align__(128) char smem[2 * BUFB];
    const u32 sb = smem_u32(smem);
    const int tid = threadIdx.x;
    const int lane = tid & 31, w = tid >> 5;
    const int bh = blockIdx.y, b = bh >> 3, h = bh & 7;
    const int q0 = blockIdx.x * 128;
    const int g = lane >> 2, c = lane & 3;

    // bias MLP coefficients (log2 domain)
    bool fastp = true;
    float cpl = 0.f, cnl = 0.f;
    #pragma unroll
    for (int j = 0; j < 8; j++) {
        float w1 = W1[j], w2v = W2[h * 8 + j];
        fastp = fastp && (b1[j] == 0.0f);
        float cc = w2v * w1;
        cpl += cc * (w1 > 0.f ? 1.0f : 0.01f);
        cnl += cc * (w1 < 0.f ? 1.0f : 0.01f);
    }
    const float b2raw = b2[h];
    const float b2hl = b2raw * (float)LOG2E;
    cpl *= (float)LOG2E; cnl *= (float)LOG2E;

    // ---- stage Q (hi/lo) into buffer 1, extract A-fragments ----
    {
        int row = tid >> 1, seg = tid & 1;
        const uint4* sh = (const uint4*)(g_Qhi + ((size_t)bh * NSEQ + q0 + row) * DH + seg * 16);
        const uint4* sl = (const uint4*)(g_Qlo + ((size_t)bh * NSEQ + q0 + row) * DH + seg * 16);
        uint4 h0 = sh[0], h1 = sh[1];
        uint4 l0 = sl[0], l1 = sl[1];
        char* d0 = smem + QH_OFF + row * ROWB + seg * 32;
        *(uint4*)d0 = h0; *(uint4*)(d0 + 16) = h1;
        char* d1 = smem + QL_OFF + row * ROWB + seg * 32;
        *(uint4*)d1 = l0; *(uint4*)(d1 + 16) = l1;
    }
    __syncthreads();
    u32 qh[2][4], ql[2][4];
    {
        int j = lane >> 3, r = lane & 7;
        int qrow = 16 * w + (j & 1) * 8 + r;
        u32 base = sb + qrow * ROWB + ((j >> 1) * 8) * 2;
        ldsm4(qh[0][0], qh[0][1], qh[0][2], qh[0][3], base + QH_OFF);
        ldsm4(qh[1][0], qh[1][1], qh[1][2], qh[1][3], base + QH_OFF + 32);
        ldsm4(ql[0][0], ql[0][1], ql[0][2], ql[0][3], base + QL_OFF);
        ldsm4(ql[1][0], ql[1][1], ql[1][2], ql[1][3], base + QL_OFF + 32);
    }

    const __nv_bfloat16* Kh = g_Khi + (size_t)bh * NSEQ * DH;
    const __nv_bfloat16* Kl = g_Klo + (size_t)bh * NSEQ * DH;
    const __nv_bfloat16* Vh = g_Vhi + (size_t)bh * NSEQ * DH;
    const __nv_bfloat16* Vl = g_Vlo + (size_t)bh * NSEQ * DH;
    const int lrow = tid >> 2, lq = tid & 3;
    const size_t loff = (size_t)lrow * DH + lq * 8;
    const u32 sdst = lrow * ROWB + lq * 16;

    // tile 0 -> buffer 0 (no one reads buffer 0 before the barrier below)
    {
        uint4 tkh = *(const uint4*)(Kh + loff);
        uint4 tkl = *(const uint4*)(Kl + loff);
        uint4 tvh = *(const uint4*)(Vh + loff);
        uint4 tvl = *(const uint4*)(Vl + loff);
        *(uint4*)(smem + KH_OFF + sdst) = tkh;
        *(uint4*)(smem + KL_OFF + sdst) = tkl;
        *(uint4*)(smem + VH_OFF + sdst) = tvh;
        *(uint4*)(smem + VL_OFF + sdst) = tvl;
    }
    __syncthreads();   // Q frags read by all; tile 0 visible

    const float* Ar = A + ((size_t)b * NSEQ + q0 + 16 * w + g) * NSEQ;

    float o[4][4] = {};
    float l0s = 0.f, l1s = 0.f;

    for (int kt = 0; kt < NSEQ / 64; kt++) {
        // issue next tile's loads early (latency overlapped with compute)
        uint4 tkh, tkl, tvh, tvl;
        const bool more = (kt + 1 < NSEQ / 64);
        if (more) {
            size_t off2 = (size_t)(kt + 1) * 64 * DH + loff;
            tkh = *(const uint4*)(Kh + off2);
            tkl = *(const uint4*)(Kl + off2);
            tvh = *(const uint4*)(Vh + off2);
            tvl = *(const uint4*)(Vl + off2);
        }
        const u32 cb = sb + (u32)(kt & 1) * BUFB;     // compute buffer
        const int k0 = kt * 64;

        // ---- S = QK^T (3-split) + bias, exp2, pack P frags ----
        u32 ph[8][2], pl[8][2];
        float2 a01 = *(const float2*)(Ar + k0 + 2 * c);
        float2 a23 = *(const float2*)(Ar + 8 * NSEQ + k0 + 2 * c);
        #pragma unroll
        for (int nt = 0; nt < 8; nt++) {
            u32 kaddr = cb + KH_OFF + (8 * nt + (lane & 7)) * ROWB + (lane >> 3) * 16;
            u32 kb0, kb1, kb2, kb3, kc0, kc1, kc2, kc3;
            ldsm4(kb0, kb1, kb2, kb3, kaddr);
            ldsm4(kc0, kc1, kc2, kc3, kaddr + (KL_OFF - KH_OFF));
            float s[4] = {0.f, 0.f, 0.f, 0.f};
            mma16816(s, qh[0], kb0, kb1);
            mma16816(s, qh[1], kb2, kb3);
            mma16816(s, ql[0], kb0, kb1);
            mma16816(s, ql[1], kb2, kb3);
            mma16816(s, qh[0], kc0, kc1);
            mma16816(s, qh[1], kc2, kc3);
            float2 na01, na23;
            if (nt < 7) {
                na01 = *(const float2*)(Ar + k0 + 8 * (nt + 1) + 2 * c);
                na23 = *(const float2*)(Ar + 8 * NSEQ + k0 + 8 * (nt + 1) + 2 * c);
            }
            float av[4] = { a01.x, a01.y, a23.x, a23.y };
            float p[4];
            #pragma unroll
            for (int e = 0; e < 4; e++) {
                float a = av[e];
                float bias;
                if (fastp) {
                    bias = fmaf(a, a > 0.f ? cpl : cnl, b2hl);
                } else {
                    float t = 0.f;
                    #pragma unroll
                    for (int jj = 0; jj < 8; jj++) {
                        float u = fmaf(a, W1[jj], b1[jj]);
                        u = fmaxf(u, 0.01f * u);
                        t = fmaf(W2[h * 8 + jj], u, t);
                    }
                    bias = (t + b2raw) * (float)LOG2E;
                }
                p[e] = ex2(s[e] + bias);
            }
            l0s += p[0] + p[1];
            l1s += p[2] + p[3];
            ph[nt][0] = packsplit(p[0], p[1], pl[nt][0]);
            ph[nt][1] = packsplit(p[2], p[3], pl[nt][1]);
            a01 = na01; a23 = na23;
        }

        // ---- O += P V (3-split), paired m16n8k16 over 16-key chunks ----
        #pragma unroll
        for (int t = 0; t < 4; t++) {
            u32 va0 = cb + VH_OFF + (16 * t + (lane & 7)) * ROWB + (lane >> 3) * 16;
            u32 va1 = va0 + 8 * ROWB;
            u32 vh0a, vh1a, vh2a, vh3a, vh0b, vh1b, vh2b, vh3b;
            u32 vl0a, vl1a, vl2a, vl3a, vl0b, vl1b, vl2b, vl3b;
            ldsm4t(vh0a, vh1a, vh2a, vh3a, va0);
            ldsm4t(vh0b, vh1b, vh2b, vh3b, va1);
            ldsm4t(vl0a, vl1a, vl2a, vl3a, va0 + (VL_OFF - VH_OFF));
            ldsm4t(vl0b, vl1b, vl2b, vl3b, va1 + (VL_OFF - VH_OFF));
            u32 Ah[4] = { ph[2 * t][0], ph[2 * t][1], ph[2 * t + 1][0], ph[2 * t + 1][1] };
            u32 Al[4] = { pl[2 * t][0], pl[2 * t][1], pl[2 * t + 1][0], pl[2 * t + 1][1] };
            mma16816(o[0], Ah, vh0a, vh0b);
            mma16816(o[1], Ah, vh1a, vh1b);
            mma16816(o[2], Ah, vh2a, vh2b);
            mma16816(o[3], Ah, vh3a, vh3b);
            mma16816(o[0], Ah, vl0a, vl0b);
            mma16816(o[1], Ah, vl1a, vl1b);
            mma16816(o[2], Ah, vl2a, vl2b);
            mma16816(o[3], Ah, vl3a, vl3b);
            mma16816(o[0], Al, vh0a, vh0b);
            mma16816(o[1], Al, vh1a, vh1b);
            mma16816(o[2], Al, vh2a, vh2b);
            mma16816(o[3], Al, vh3a, vh3b);
        }

        // store next tile into the other buffer, then single barrier
        if (more) {
            char* nb = smem + ((kt + 1) & 1) * BUFB;
            *(uint4*)(nb + KH_OFF + sdst) = tkh;
            *(uint4*)(nb + KL_OFF + sdst) = tkl;
            *(uint4*)(nb + VH_OFF + sdst) = tvh;
            *(uint4*)(nb + VL_OFF + sdst) = tvl;
        }
        __syncthreads();
    }

    // ---- reduce row sums across the 4 lanes of each row, write O hi/lo ----
    l0s += __shfl_xor_sync(0xffffffffu, l0s, 1);
    l0s += __shfl_xor_sync(0xffffffffu, l0s, 2);
    l1s += __shfl_xor_sync(0xffffffffu, l1s, 1);
    l1s += __shfl_xor_sync(0xffffffffu, l1s, 2);
    float i0 = 1.0f / l0s, i1 = 1.0f / l1s;
    int r0g = q0 + 16 * w + g;
    size_t base0 = ((size_t)b * NSEQ + r0g) * DMODEL + h * DH;
    size_t base1 = base0 + 8 * DMODEL;
    #pragma unroll
    for (int ng = 0; ng < 4; ng++) {
        u32 lw, hw;
        hw = packsplit(o[ng][0] * i0, o[ng][1] * i0, lw);
        *(u32*)(g_Ohi + base0 + 8 * ng + 2 * c) = hw;
        *(u32*)(g_Olo + base0 + 8 * ng + 2 * c) = lw;
        hw = packsplit(o[ng][2] * i1, o[ng][3] * i1, lw);
        *(u32*)(g_Ohi + base1 + 8 * ng + 2 * c) = hw;
        *(u32*)(g_Olo + base1 + 8 * ng + 2 * c) = lw;
    }
}

extern "C" void kernel_launch(void* const* d_in, const int* in_sizes, int n_in,
                              void* d_out, int out_size)
{
    const float* x  = (const float*)d_in[0];
    const float* A  = (const float*)d_in[1];
    const float* Wq = (const float*)d_in[2];
    const float* bq = (const float*)d_in[3];
    const float* Wk = (const float*)d_in[4];
    const float* bk = (const float*)d_in[5];
    const float* Wv = (const float*)d_in[6];
    const float* bv = (const float*)d_in[7];
    const float* Wo = (const float*)d_in[8];
    const float* bo = (const float*)d_in[9];
    const float* W1 = (const float*)d_in[10];
    const float* b1 = (const float*)d_in[11];
    const float* W2 = (const float*)d_in[12];
    const float* b2 = (const float*)d_in[13];
    float* out = (float*)d_out;

    convert_split<<<dim3(2048, 1, 5), 256>>>(x, Wq, Wk, Wv, Wo);
    proj_tc<<<dim3(DMODEL / 64, MROWS / 64, 3), 256>>>(bq, bk, bv, bo, out, 0);
    attn_mma<<<dim3(NSEQ / 128, NBH), 256>>>(A, W1, b1, W2, b2);
    proj_tc<<<dim3(DMODEL / 64, MROWS / 64, 1), 256>>>(bq, bk, bv, bo, out, 3);
}

// round 10
// speedup vs baseline: 1.6205x; 1.2430x over previous
#include <cuda_runtime.h>
#include <cuda_fp16.h>

#define BDIM 2
#define NSEQ 2048
#define DMODEL 256
#define HHEADS 8
#define DH 32
#define MROWS (BDIM*NSEQ)   // 4096
#define NBH (BDIM*HHEADS)   // 16

#define LOG2E 1.4426950408889634
#define QSCALE ((float)(1.4426950408889634/5.656854249492381))  // log2e/sqrt(32)

typedef unsigned long long u64;
typedef unsigned int u32;

// ---------------- scratch (__device__ globals; no allocations) --------------
__device__ __align__(16) __half g_Qhi[NBH*NSEQ*DH];
__device__ __align__(16) __half g_Qlo[NBH*NSEQ*DH];
__device__ __align__(16) __half g_Khi[NBH*NSEQ*DH];          // K: single fp16
__device__ __align__(16) __half g_Vhi[NBH*NSEQ*DH];          // [bh][n][d]
__device__ __align__(16) __half g_Vlo[NBH*NSEQ*DH];
__device__ __align__(16) __half g_Ohi[MROWS*DMODEL];
__device__ __align__(16) __half g_Olo[MROWS*DMODEL];
__device__ __align__(16) __half g_xhi[MROWS*DMODEL];
__device__ __align__(16) __half g_xlo[MROWS*DMODEL];
__device__ __align__(16) __half g_wh[4*DMODEL*DMODEL];       // q,k,v,o  (single fp16)

// ---------------- helpers ---------------------------------------------------
__device__ __forceinline__ u32 smem_u32(const void* p) {
    u32 a; asm("{ .reg .u64 t; cvta.to.shared.u64 t, %1; cvt.u32.u64 %0, t; }" : "=r"(a) : "l"(p));
    return a;
}
__device__ __forceinline__ void ldsm4(u32 &r0, u32 &r1, u32 &r2, u32 &r3, u32 a) {
    asm volatile("ldmatrix.sync.aligned.m8n8.x4.shared.b16 {%0,%1,%2,%3}, [%4];"
                 : "=r"(r0), "=r"(r1), "=r"(r2), "=r"(r3) : "r"(a));
}
__device__ __forceinline__ void ldsm4t(u32 &r0, u32 &r1, u32 &r2, u32 &r3, u32 a) {
    asm volatile("ldmatrix.sync.aligned.m8n8.x4.trans.shared.b16 {%0,%1,%2,%3}, [%4];"
                 : "=r"(r0), "=r"(r1), "=r"(r2), "=r"(r3) : "r"(a));
}
__device__ __forceinline__ void mma16816(float* d, const u32* a, u32 b0, u32 b1) {
    asm volatile("mma.sync.aligned.m16n8k16.row.col.f32.f16.f16.f32 "
                 "{%0,%1,%2,%3}, {%4,%5,%6,%7}, {%8,%9}, {%0,%1,%2,%3};"
                 : "+f"(d[0]), "+f"(d[1]), "+f"(d[2]), "+f"(d[3])
                 : "r"(a[0]), "r"(a[1]), "r"(a[2]), "r"(a[3]), "r"(b0), "r"(b1));
}
__device__ __forceinline__ float ex2(float x) {
    float r; asm("ex2.approx.ftz.f32 %0, %1;" : "=f"(r) : "f"(x)); return r;
}
__device__ __forceinline__ u32 packh(float a, float b) {
    __half2 t = __floats2half2_rn(a, b);     // low = a
    return *(u32*)&t;
}
__device__ __forceinline__ u32 packsplith(float v0, float v1, u32 &lw) {
    u32 hw = packh(v0, v1);
    __half2 hv = *(__half2*)&hw;
    float e0 = __half2float(__low2half(hv));
    float e1 = __half2float(__high2half(hv));
    lw = packh(v0 - e0, v1 - e1);
    return hw;
}

// ---------------------------------------------------------------------------
// Convert fp32 -> fp16: x as hi/lo pair; the 4 weight matrices as single fp16.
// ---------------------------------------------------------------------------
__global__ __launch_bounds__(256) void convert_split(
    const float* __restrict__ x, const float* __restrict__ Wq,
    const float* __restrict__ Wk, const float* __restrict__ Wv,
    const float* __restrict__ Wo)
{
    const int z = blockIdx.z;
    if (z == 0) {
        int i = (blockIdx.x * 256 + threadIdx.x) * 2;
        if (i >= MROWS * DMODEL) return;
        float2 v = *(const float2*)(x + i);
        u32 lw, hw = packsplith(v.x, v.y, lw);
        *(u32*)(g_xhi + i) = hw;
        *(u32*)(g_xlo + i) = lw;
    } else {
        const float* src = (z == 1) ? Wq : (z == 2) ? Wk : (z == 3) ? Wv : Wo;
        __half* dh = g_wh + (size_t)(z - 1) * DMODEL * DMODEL;
        int i = (blockIdx.x * 256 + threadIdx.x) * 2;
        if (i >= DMODEL * DMODEL) return;
        float2 v = *(const float2*)(src + i);
        *(u32*)(dh + i) = packh(v.x, v.y);
    }
}

// ---------------------------------------------------------------------------
// Tensor-core projection: C = X @ W^T + bias, fp16 2-term (Xhi+Xlo)*Whi.
// mode = base_mode + blockIdx.z: 0=Q (scaled, hi/lo), 1=K (hi only),
// 2=V (hi/lo), 3=out (fp32). BM=64, BN=64, BK=32. 256 thr / 8 warps.
// ---------------------------------------------------------------------------
#define PRB 80       // smem row stride bytes (64B data + pad)
#define PXH 0
#define PXL 5120
#define PWH 10240

__global__ __launch_bounds__(256, 3) void proj_tc(
    const float* __restrict__ bq, const float* __restrict__ bk,
    const float* __restrict__ bv, const float* __restrict__ bo,
    float* __restrict__ outf, int base_mode)
{
    __shared__ __align__(128) char sm[15360];
    const u32 sb = smem_u32(sm);
    const int mode = base_mode + blockIdx.z;
    const __half *Xh, *Xl;
    if (mode < 3) { Xh = g_xhi; Xl = g_xlo; } else { Xh = g_Ohi; Xl = g_Olo; }
    const __half* Wh = g_wh + (size_t)mode * DMODEL * DMODEL;
    const float* bias = (mode == 0) ? bq : (mode == 1) ? bk : (mode == 2) ? bv : bo;

    const int tid = threadIdx.x, lane = tid & 31, w = tid >> 5;
    const int wr = w & 3, wc = w >> 2;
    const int row0 = blockIdx.y * 64, col0 = blockIdx.x * 64;

    const int xr = tid >> 2, xs = tid & 3;

    const __half* pxh = Xh + (size_t)(row0 + xr) * DMODEL + xs * 8;
    const __half* pxl = Xl + (size_t)(row0 + xr) * DMODEL + xs * 8;
    const __half* pwh = Wh + (size_t)(col0 + xr) * DMODEL + xs * 8;

    uint4 rxh = *(const uint4*)pxh, rxl = *(const uint4*)pxl;
    uint4 rwh = *(const uint4*)pwh;

    float acc[4][4] = {};
    const int j = lane >> 3, r = lane & 7;
    const u32 abase = sb + PXH + (u32)(16 * wr + (j & 1) * 8 + r) * PRB + (u32)(j >> 1) * 16;
    const u32 wbase = sb + PWH + (u32)(32 * wc + (lane & 15)) * PRB + (u32)(lane >> 4) * 16;

    for (int kt = 0; kt < 8; kt++) {
        __syncthreads();
        *(uint4*)(sm + PXH + xr * PRB + xs * 16) = rxh;
        *(uint4*)(sm + PXL + xr * PRB + xs * 16) = rxl;
        *(uint4*)(sm + PWH + xr * PRB + xs * 16) = rwh;
        __syncthreads();
        if (kt < 7) {
            int ko = (kt + 1) * 32;
            rxh = *(const uint4*)(pxh + ko); rxl = *(const uint4*)(pxl + ko);
            rwh = *(const uint4*)(pwh + ko);
        }
        u32 ah[2][4], al[2][4];
        ldsm4(ah[0][0], ah[0][1], ah[0][2], ah[0][3], abase);
        ldsm4(ah[1][0], ah[1][1], ah[1][2], ah[1][3], abase + 32);
        ldsm4(al[0][0], al[0][1], al[0][2], al[0][3], abase + (PXL - PXH));
        ldsm4(al[1][0], al[1][1], al[1][2], al[1][3], abase + (PXL - PXH) + 32);
        #pragma unroll
        for (int ng = 0; ng < 2; ng++) {
            #pragma unroll
            for (int kc = 0; kc < 2; kc++) {
                u32 wb = wbase + (u32)(16 * ng) * PRB + kc * 32;
                u32 h0, h1, h2, h3;
                ldsm4(h0, h1, h2, h3, wb);
                mma16816(acc[2 * ng],     ah[kc], h0, h2);
                mma16816(acc[2 * ng],     al[kc], h0, h2);
                mma16816(acc[2 * ng + 1], ah[kc], h1, h3);
                mma16816(acc[2 * ng + 1], al[kc], h1, h3);
            }
        }
    }

    // epilogue
    const int g = lane >> 2, c = lane & 3;
    const int m0 = row0 + 16 * wr + g;
    #pragma unroll
    for (int half = 0; half < 2; half++) {
        int m = m0 + 8 * half;
        int bb = m >> 11, n = m & (NSEQ - 1);
        #pragma unroll
        for (int nn = 0; nn < 4; nn++) {
            int col = col0 + 32 * wc + 8 * nn + 2 * c;
            float v0 = acc[nn][2 * half + 0] + bias[col];
            float v1 = acc[nn][2 * half + 1] + bias[col + 1];
            if (mode == 3) {
                *(float2*)(outf + (size_t)m * DMODEL + col) = make_float2(v0, v1);
            } else {
                int hh = col >> 5, d = col & 31;
                size_t idx = (((size_t)(bb * HHEADS + hh)) * NSEQ + n) * DH + d;
                if (mode == 1) {
                    *(u32*)(g_Khi + idx) = packh(v0, v1);
                } else {
                    if (mode == 0) { v0 *= QSCALE; v1 *= QSCALE; }
                    u32 lw, hw = packsplith(v0, v1, lw);
                    __half* dsth = (mode == 0) ? g_Qhi : g_Vhi;
                    __half* dstl = (mode == 0) ? g_Qlo : g_Vlo;
                    *(u32*)(dsth + idx) = hw;
                    *(u32*)(dstl + idx) = lw;
                }
            }
        }
    }
}

// ---------------------------------------------------------------------------
// mma.sync flash attention, fp16. S = (Qhi+Qlo)*Khi; PV = Phi*(Vhi,Vlo).
// Double-buffered K/V smem; one __syncthreads per k-tile; reg prefetch.
// Grid (16 q-tiles, 16 bh), 256 threads / 8 warps; warp owns 16 query rows.
// Q staging: QH in buffer0[0..10240), QL in buffer1[0..10240), consumed into
// registers (ldsm) before any K/V tile is written.
// ---------------------------------------------------------------------------
#define ROWB 80
#define BUFB 15360          // bytes per K/V buffer
#define KH_OFF 0
#define VH_OFF 5120
#define VL_OFF 10240

__global__ __launch_bounds__(256, 2) void attn_mma(
    const float* __restrict__ A,
    const float* __restrict__ W1, const float* __restrict__ b1,
    const float* __restrict__ W2, const float* __restrict__ b2)
{
    __shared__ __align__(128) char smem[2 * BUFB];
    const u32 sb = smem_u32(smem);
    const int tid = threadIdx.x;
    const int lane = tid & 31, w = tid >> 5;
    const int bh = blockIdx.y, b = bh >> 3, h = bh & 7;
    const int q0 = blockIdx.x * 128;
    const int g = lane >> 2, c = lane & 3;

    // bias MLP coefficients (log2 domain)
    bool fastp = true;
    float cpl = 0.f, cnl = 0.f;
    #pragma unroll
    for (int j = 0; j < 8; j++) {
        float w1 = W1[j], w2v = W2[h * 8 + j];
        fastp = fastp && (b1[j] == 0.0f);
        float cc = w2v * w1;
        cpl += cc * (w1 > 0.f ? 1.0f : 0.01f);
        cnl += cc * (w1 < 0.f ? 1.0f : 0.01f);
    }
    const float b2raw = b2[h];
    const float b2hl = b2raw * (float)LOG2E;
    cpl *= (float)LOG2E; cnl *= (float)LOG2E;

    // ---- stage Q: QH -> buffer0, QL -> buffer1 (full 64B rows) ----
    {
        int row = tid >> 1, seg = tid & 1;     // seg selects 32B half of 64B row
        const uint4* sh = (const uint4*)(g_Qhi + ((size_t)bh * NSEQ + q0 + row) * DH + seg * 16);
        const uint4* sl = (const uint4*)(g_Qlo + ((size_t)bh * NSEQ + q0 + row) * DH + seg * 16);
        uint4 h0 = sh[0], h1 = sh[1];
        uint4 l0 = sl[0], l1 = sl[1];
        char* d0 = smem + row * ROWB + seg * 32;
        *(uint4*)d0 = h0; *(uint4*)(d0 + 16) = h1;
        char* d1 = smem + BUFB + row * ROWB + seg * 32;
        *(uint4*)d1 = l0; *(uint4*)(d1 + 16) = l1;
    }
    __syncthreads();
    u32 qh[2][4], ql[2][4];
    {
        int j = lane >> 3, r = lane & 7;
        int qrow = 16 * w + (j & 1) * 8 + r;
        u32 base = sb + qrow * ROWB + (u32)(j >> 1) * 16;
        ldsm4(qh[0][0], qh[0][1], qh[0][2], qh[0][3], base);
        ldsm4(qh[1][0], qh[1][1], qh[1][2], qh[1][3], base + 32);
        ldsm4(ql[0][0], ql[0][1], ql[0][2], ql[0][3], base + BUFB);
        ldsm4(ql[1][0], ql[1][1], ql[1][2], ql[1][3], base + BUFB + 32);
    }
    __syncthreads();   // Q staging fully consumed; buffers now free for K/V

    const __half* Kh = g_Khi + (size_t)bh * NSEQ * DH;
    const __half* Vh = g_Vhi + (size_t)bh * NSEQ * DH;
    const __half* Vl = g_Vlo + (size_t)bh * NSEQ * DH;
    const int lrow = tid >> 2, lq = tid & 3;
    const size_t loff = (size_t)lrow * DH + lq * 8;     // 8 fp16 = 16B
    const u32 sdst = lrow * ROWB + lq * 16;

    // tile 0 -> buffer 0
    {
        uint4 tkh = *(const uint4*)(Kh + loff);
        uint4 tvh = *(const uint4*)(Vh + loff);
        uint4 tvl = *(const uint4*)(Vl + loff);
        *(uint4*)(smem + KH_OFF + sdst) = tkh;
        *(uint4*)(smem + VH_OFF + sdst) = tvh;
        *(uint4*)(smem + VL_OFF + sdst) = tvl;
    }
    __syncthreads();   // tile 0 visible

    const float* Ar = A + ((size_t)b * NSEQ + q0 + 16 * w + g) * NSEQ;

    float o[4][4] = {};
    float l0s = 0.f, l1s = 0.f;

    for (int kt = 0; kt < NSEQ / 64; kt++) {
        // issue next tile's loads early (latency overlapped with compute)
        uint4 tkh, tvh, tvl;
        const bool more = (kt + 1 < NSEQ / 64);
        if (more) {
            size_t off2 = (size_t)(kt + 1) * 64 * DH + loff;
            tkh = *(const uint4*)(Kh + off2);
            tvh = *(const uint4*)(Vh + off2);
            tvl = *(const uint4*)(Vl + off2);
        }
        const u32 cb = sb + (u32)(kt & 1) * BUFB;     // compute buffer
        const int k0 = kt * 64;

        // ---- S = QK^T (2-term) + bias, exp2, pack P frags (fp16) ----
        u32 ph[8][2];
        float2 a01 = *(const float2*)(Ar + k0 + 2 * c);
        float2 a23 = *(const float2*)(Ar + 8 * NSEQ + k0 + 2 * c);
        #pragma unroll
        for (int nt = 0; nt < 8; nt++) {
            u32 kaddr = cb + KH_OFF + (8 * nt + (lane & 7)) * ROWB + (lane >> 3) * 16;
            u32 kb0, kb1, kb2, kb3;
            ldsm4(kb0, kb1, kb2, kb3, kaddr);
            float s[4] = {0.f, 0.f, 0.f, 0.f};
            mma16816(s, qh[0], kb0, kb1);
            mma16816(s, qh[1], kb2, kb3);
            mma16816(s, ql[0], kb0, kb1);
            mma16816(s, ql[1], kb2, kb3);
            float2 na01, na23;
            if (nt < 7) {
                na01 = *(const float2*)(Ar + k0 + 8 * (nt + 1) + 2 * c);
                na23 = *(const float2*)(Ar + 8 * NSEQ + k0 + 8 * (nt + 1) + 2 * c);
            }
            float av[4] = { a01.x, a01.y, a23.x, a23.y };
            float p[4];
            #pragma unroll
            for (int e = 0; e < 4; e++) {
                float a = av[e];
                float bias;
                if (fastp) {
                    bias = fmaf(a, a > 0.f ? cpl : cnl, b2hl);
                } else {
                    float t = 0.f;
                    #pragma unroll
                    for (int jj = 0; jj < 8; jj++) {
                        float u = fmaf(a, W1[jj], b1[jj]);
                        u = fmaxf(u, 0.01f * u);
                        t = fmaf(W2[h * 8 + jj], u, t);
                    }
                    bias = (t + b2raw) * (float)LOG2E;
                }
                p[e] = ex2(s[e] + bias);
            }
            l0s += p[0] + p[1];
            l1s += p[2] + p[3];
            ph[nt][0] = packh(p[0], p[1]);
            ph[nt][1] = packh(p[2], p[3]);
            a01 = na01; a23 = na23;
        }

        // ---- O += P V (2-term: Vhi, Vlo), paired m16n8k16 over 16 keys ----
        #pragma unroll
        for (int t = 0; t < 4; t++) {
            u32 va0 = cb + VH_OFF + (16 * t + (lane & 7)) * ROWB + (lane >> 3) * 16;
            u32 va1 = va0 + 8 * ROWB;
            u32 vh0a, vh1a, vh2a, vh3a, vh0b, vh1b, vh2b, vh3b;
            u32 vl0a, vl1a, vl2a, vl3a, vl0b, vl1b, vl2b, vl3b;
            ldsm4t(vh0a, vh1a, vh2a, vh3a, va0);
            ldsm4t(vh0b, vh1b, vh2b, vh3b, va1);
            ldsm4t(vl0a, vl1a, vl2a, vl3a, va0 + (VL_OFF - VH_OFF));
            ldsm4t(vl0b, vl1b, vl2b, vl3b, va1 + (VL_OFF - VH_OFF));
            u32 Ah[4] = { ph[2 * t][0], ph[2 * t][1], ph[2 * t + 1][0], ph[2 * t + 1][1] };
            mma16816(o[0], Ah, vh0a, vh0b);
            mma16816(o[1], Ah, vh1a, vh1b);
            mma16816(o[2], Ah, vh2a, vh2b);
            mma16816(o[3], Ah, vh3a, vh3b);
            mma16816(o[0], Ah, vl0a, vl0b);
            mma16816(o[1], Ah, vl1a, vl1b);
            mma16816(o[2], Ah, vl2a, vl2b);
            mma16816(o[3], Ah, vl3a, vl3b);
        }

        // store next tile into the other buffer, then single barrier
        if (more) {
            char* nb = smem + ((kt + 1) & 1) * BUFB;
            *(uint4*)(nb + KH_OFF + sdst) = tkh;
            *(uint4*)(nb + VH_OFF + sdst) = tvh;
            *(uint4*)(nb + VL_OFF + sdst) = tvl;
        }
        __syncthreads();
    }

    // ---- reduce row sums across the 4 lanes of each row, write O hi/lo ----
    l0s += __shfl_xor_sync(0xffffffffu, l0s, 1);
    l0s += __shfl_xor_sync(0xffffffffu, l0s, 2);
    l1s += __shfl_xor_sync(0xffffffffu, l1s, 1);
    l1s += __shfl_xor_sync(0xffffffffu, l1s, 2);
    float i0 = 1.0f / l0s, i1 = 1.0f / l1s;
    int r0g = q0 + 16 * w + g;
    size_t base0 = ((size_t)b * NSEQ + r0g) * DMODEL + h * DH;
    size_t base1 = base0 + 8 * DMODEL;
    #pragma unroll
    for (int ng = 0; ng < 4; ng++) {
        u32 lw, hw;
        hw = packsplith(o[ng][0] * i0, o[ng][1] * i0, lw);
        *(u32*)(g_Ohi + base0 + 8 * ng + 2 * c) = hw;
        *(u32*)(g_Olo + base0 + 8 * ng + 2 * c) = lw;
        hw = packsplith(o[ng][2] * i1, o[ng][3] * i1, lw);
        *(u32*)(g_Ohi + base1 + 8 * ng + 2 * c) = hw;
        *(u32*)(g_Olo + base1 + 8 * ng + 2 * c) = lw;
    }
}

extern "C" void kernel_launch(void* const* d_in, const int* in_sizes, int n_in,
                              void* d_out, int out_size)
{
    const float* x  = (const float*)d_in[0];
    const float* A  = (const float*)d_in[1];
    const float* Wq = (const float*)d_in[2];
    const float* bq = (const float*)d_in[3];
    const float* Wk = (const float*)d_in[4];
    const float* bk = (const float*)d_in[5];
    const float* Wv = (const float*)d_in[6];
    const float* bv = (const float*)d_in[7];
    const float* Wo = (const float*)d_in[8];
    const float* bo = (const float*)d_in[9];
    const float* W1 = (const float*)d_in[10];
    const float* b1 = (const float*)d_in[11];
    const float* W2 = (const float*)d_in[12];
    const float* b2 = (const float*)d_in[13];
    float* out = (float*)d_out;

    convert_split<<<dim3(2048, 1, 5), 256>>>(x, Wq, Wk, Wv, Wo);
    proj_tc<<<dim3(DMODEL / 64, MROWS / 64, 3), 256>>>(bq, bk, bv, bo, out, 0);
    attn_mma<<<dim3(NSEQ / 128, NBH), 256>>>(A, W1, b1, W2, b2);
    proj_tc<<<dim3(DMODEL / 64, MROWS / 64, 1), 256>>>(bq, bk, bv, bo, out, 3);
}